// round 1
// baseline (speedup 1.0000x reference)
#include <cuda_runtime.h>

// NonSpikingInput: v' = v + DT*k2, which collapses to v' = A*v + B*i
// with A = 1 - G*DT*0.75 = 0.625, B = DT*0.75 = 0.075.
// Contractive recurrence (A^64 ~ 8.6e-14) -> chunk the time axis, each
// thread warm-starts 64 steps before its chunk from v=0.

#define NN    4096
#define TT    8192
#define CHUNK 256            // timesteps per thread
#define NCHUNK (TT / CHUNK)  // 32 chunks per neuron
#define WARM  64             // warm-up steps (A^64 << fp32 eps)

__global__ __launch_bounds__(256)
void nonspiking_scan_kernel(const float* __restrict__ in, float* __restrict__ out)
{
    const float A = 0.625f;
    const float B = 0.075f;

    int tid = blockIdx.x * blockDim.x + threadIdx.x;
    int n = tid >> 5;        // neuron (warp covers 32 chunks of ONE row -> L2 locality)
    int c = tid & (NCHUNK - 1);

    const float4* rp = reinterpret_cast<const float4*>(in + (size_t)n * TT);
    float4*       wp = reinterpret_cast<float4*>(out + (size_t)n * TT);

    int base4 = c * (CHUNK / 4);
    float v = 0.0f;

    if (c != 0) {
        // Warm-up: 64 steps (16 float4), no stores. Fully unrolled -> ptxas
        // front-batches the 16 independent LDG.128 (high MLP at chunk start).
        const float4* p = rp + base4 - (WARM / 4);
        #pragma unroll
        for (int j = 0; j < WARM / 4; ++j) {
            float4 x = p[j];
            v = fmaf(A, v, B * x.x);
            v = fmaf(A, v, B * x.y);
            v = fmaf(A, v, B * x.z);
            v = fmaf(A, v, B * x.w);
        }
    }

    const float4* p = rp + base4;
    float4*       q = wp + base4;
    #pragma unroll 8
    for (int j = 0; j < CHUNK / 4; ++j) {
        float4 x = p[j];
        float4 y;
        v = fmaf(A, v, B * x.x); y.x = v;
        v = fmaf(A, v, B * x.y); y.y = v;
        v = fmaf(A, v, B * x.z); y.z = v;
        v = fmaf(A, v, B * x.w); y.w = v;
        q[j] = y;
    }
}

extern "C" void kernel_launch(void* const* d_in, const int* in_sizes, int n_in,
                              void* d_out, int out_size)
{
    const float* in = (const float*)d_in[0];
    float* out = (float*)d_out;
    (void)in_sizes; (void)n_in; (void)out_size;

    int total_threads = NN * NCHUNK;        // 131072
    int block = 256;
    int grid = total_threads / block;       // 512
    nonspiking_scan_kernel<<<grid, block>>>(in, out);
}

// round 2
// speedup vs baseline: 2.2424x; 2.2424x over previous
#include <cuda_runtime.h>

// v' = A*v + B*i  (A = 1 - G*DT*0.75 = 0.625, B = DT*0.75 = 0.075)
// Warp-cooperative affine scan: each 128-element tile is loaded coalesced
// (lane -> one float4), scanned via Kogge-Stone over affine maps where the
// step-s multiplier is the compile-time constant A^(4s), stored coalesced.
// Time axis chunked 4-ways per row with a 128-step warm-up tile
// (truncation error factor A^128 ~ 7.5e-27 -> exact in fp32).

#define NN     4096
#define TT     8192
#define TILE   128                 // elements per warp-tile (32 lanes x float4)
#define CHUNK  2048                // elements per warp
#define TILES  (CHUNK / TILE)      // 16
#define NCHUNK (TT / CHUNK)        // 4 chunks per row

#define A1f 0.625f
#define A2f 0.390625f
#define A3f 0.244140625f
#define A4f 0.152587890625f
#define A8f 2.3283064365386963e-2f
#define A16f 5.4210108624275222e-4f
#define A32f 2.9387358770557188e-7f
#define A64f 8.6361685550944446e-14f
#define A128f 7.4583407312002067e-27f
#define Bf  0.075f

// Scan one 128-element tile. Returns the carry (v after the tile's last step).
template <bool STORE>
__device__ __forceinline__ float warp_tile_scan(const float4* __restrict__ p,
                                                float4* __restrict__ q,
                                                float carry, float apl, int lane)
{
    float4 x = p[lane];                       // coalesced 512B warp load
    // local cumulative terms (v contribution from this lane's 4 inputs)
    float c0 = Bf * x.x;
    float c1 = fmaf(A1f, c0, Bf * x.y);
    float c2 = fmaf(A1f, c1, Bf * x.z);
    float c3 = fmaf(A1f, c2, Bf * x.w);
    float b = c3;                             // lane summary: f(v) = A^4 v + b

    // Kogge-Stone inclusive scan of affine maps; multiplier at step s = A^(4s)
    float t;
    t = __shfl_up_sync(0xffffffffu, b, 1);  if (lane >= 1)  b = fmaf(A4f,  t, b);
    t = __shfl_up_sync(0xffffffffu, b, 2);  if (lane >= 2)  b = fmaf(A8f,  t, b);
    t = __shfl_up_sync(0xffffffffu, b, 4);  if (lane >= 4)  b = fmaf(A16f, t, b);
    t = __shfl_up_sync(0xffffffffu, b, 8);  if (lane >= 8)  b = fmaf(A32f, t, b);
    t = __shfl_up_sync(0xffffffffu, b, 16); if (lane >= 16) b = fmaf(A64f, t, b);

    // exclusive prefix entering this lane: P = A^(4*lane)*carry + b_{lane-1}
    float bp = __shfl_up_sync(0xffffffffu, b, 1);
    if (lane == 0) bp = 0.0f;
    float P = fmaf(apl, carry, bp);

    if (STORE) {
        float4 y;
        y.x = fmaf(A1f, P, c0);
        y.y = fmaf(A2f, P, c1);
        y.z = fmaf(A3f, P, c2);
        y.w = fmaf(A4f, P, c3);
        q[lane] = y;                          // coalesced 512B warp store
    }

    // carry out = A^128 * carry + b_31
    float b31 = __shfl_sync(0xffffffffu, b, 31);
    return fmaf(A128f, carry, b31);
}

__global__ __launch_bounds__(256)
void nonspiking_warpscan_kernel(const float* __restrict__ in, float* __restrict__ out)
{
    int wid  = (blockIdx.x * blockDim.x + threadIdx.x) >> 5;
    int lane = threadIdx.x & 31;
    int n = wid / NCHUNK;                     // row (adjacent warps -> contiguous memory)
    int c = wid % NCHUNK;                     // chunk within row

    const float* row  = in  + (size_t)n * TT;
    float*       orow = out + (size_t)n * TT;
    int base = c * CHUNK;

    // apl = A^(4*lane) by square-and-multiply (once per thread)
    float apl = 1.0f, aa = A4f;
    int e = lane;
    #pragma unroll
    for (int k = 0; k < 5; ++k) { if (e & 1) apl *= aa; aa *= aa; e >>= 1; }

    float carry = 0.0f;
    if (c != 0) {
        // warm-up tile: 128 steps before the chunk, starting from v=0
        carry = warp_tile_scan<false>(
            reinterpret_cast<const float4*>(row + base - TILE), nullptr, 0.0f, apl, lane);
    }

    const float4* p = reinterpret_cast<const float4*>(row + base);
    float4*       q = reinterpret_cast<float4*>(orow + base);
    #pragma unroll 4
    for (int t = 0; t < TILES; ++t) {
        carry = warp_tile_scan<true>(p + t * 32, q + t * 32, carry, apl, lane);
    }
}

extern "C" void kernel_launch(void* const* d_in, const int* in_sizes, int n_in,
                              void* d_out, int out_size)
{
    const float* in = (const float*)d_in[0];
    float* out = (float*)d_out;
    (void)in_sizes; (void)n_in; (void)out_size;

    int total_warps = NN * NCHUNK;            // 16384
    int block = 256;                          // 8 warps
    int grid = total_warps * 32 / block;      // 2048
    nonspiking_warpscan_kernel<<<grid, block>>>(in, out);
}

// round 3
// speedup vs baseline: 2.3452x; 1.0459x over previous
#include <cuda_runtime.h>

// v' = A*v + B*i  (A = 0.625, B = 0.075), warp-cooperative affine scan.
// R3: 256-element tiles (8 floats/lane), double-buffered prefetch,
// streaming cache hints. Carry across a 256-tile is exactly b31 since
// A^256 underflows fp32.

#define NN     4096
#define TT     8192
#define CHUNK  2048
#define TILES  (CHUNK / 256)       // 8 tiles of 256
#define NCHUNK (TT / CHUNK)        // 4 chunks per row

#define A1f 0.625f
#define A2f 0.390625f
#define A3f 0.244140625f
#define A4f 0.152587890625f
#define A5f 0.095367431640625f
#define A6f 0.059604644775390625f
#define A7f 0.037252902984619140625f
#define A8f 0.02328306436538696289f
#define A16f 5.4210108624275222e-4f
#define A32f 2.9387358770557188e-7f
#define A64f 8.6361685550944446e-14f
#define A128f 7.4583407312002067e-27f
#define Bf  0.075f

// Warm-up: scan 128 elements (4/lane), return ending v (carry in = 0).
__device__ __forceinline__ float warm_tile(const float4* __restrict__ p, int lane)
{
    float4 x = __ldcs(p + lane);
    float c = Bf * x.x;
    c = fmaf(A1f, c, Bf * x.y);
    c = fmaf(A1f, c, Bf * x.z);
    c = fmaf(A1f, c, Bf * x.w);
    float b = c, t;
    t = __shfl_up_sync(0xffffffffu, b, 1);  if (lane >= 1)  b = fmaf(A4f,  t, b);
    t = __shfl_up_sync(0xffffffffu, b, 2);  if (lane >= 2)  b = fmaf(A8f,  t, b);
    t = __shfl_up_sync(0xffffffffu, b, 4);  if (lane >= 4)  b = fmaf(A16f, t, b);
    t = __shfl_up_sync(0xffffffffu, b, 8);  if (lane >= 8)  b = fmaf(A32f, t, b);
    t = __shfl_up_sync(0xffffffffu, b, 16); if (lane >= 16) b = fmaf(A64f, t, b);
    return __shfl_sync(0xffffffffu, b, 31);
}

// Scan one 256-element tile already loaded into (xa, xb). Stores results,
// returns carry-out (= b31; A^256 underflows to 0).
__device__ __forceinline__ float tile_scan256(float4 xa, float4 xb,
                                              float4* __restrict__ q,
                                              float carry, float apl, int lane)
{
    float c0 = Bf * xa.x;
    float c1 = fmaf(A1f, c0, Bf * xa.y);
    float c2 = fmaf(A1f, c1, Bf * xa.z);
    float c3 = fmaf(A1f, c2, Bf * xa.w);
    float c4 = fmaf(A1f, c3, Bf * xb.x);
    float c5 = fmaf(A1f, c4, Bf * xb.y);
    float c6 = fmaf(A1f, c5, Bf * xb.z);
    float c7 = fmaf(A1f, c6, Bf * xb.w);

    float b = c7, t;
    t = __shfl_up_sync(0xffffffffu, b, 1);  if (lane >= 1)  b = fmaf(A8f,   t, b);
    t = __shfl_up_sync(0xffffffffu, b, 2);  if (lane >= 2)  b = fmaf(A16f,  t, b);
    t = __shfl_up_sync(0xffffffffu, b, 4);  if (lane >= 4)  b = fmaf(A32f,  t, b);
    t = __shfl_up_sync(0xffffffffu, b, 8);  if (lane >= 8)  b = fmaf(A64f,  t, b);
    t = __shfl_up_sync(0xffffffffu, b, 16); if (lane >= 16) b = fmaf(A128f, t, b);

    float bp = __shfl_up_sync(0xffffffffu, b, 1);
    if (lane == 0) bp = 0.0f;
    float P = fmaf(apl, carry, bp);

    float4 ya, yb;
    ya.x = fmaf(A1f, P, c0);
    ya.y = fmaf(A2f, P, c1);
    ya.z = fmaf(A3f, P, c2);
    ya.w = fmaf(A4f, P, c3);
    yb.x = fmaf(A5f, P, c4);
    yb.y = fmaf(A6f, P, c5);
    yb.z = fmaf(A7f, P, c6);
    yb.w = fmaf(A8f, P, c7);
    __stcs(q + 2 * lane, ya);
    __stcs(q + 2 * lane + 1, yb);

    return __shfl_sync(0xffffffffu, b, 31);
}

__global__ __launch_bounds__(256)
void nonspiking_warpscan256_kernel(const float* __restrict__ in, float* __restrict__ out)
{
    int wid  = (blockIdx.x * blockDim.x + threadIdx.x) >> 5;
    int lane = threadIdx.x & 31;
    int n = wid / NCHUNK;
    int c = wid % NCHUNK;

    const float* row  = in  + (size_t)n * TT;
    float*       orow = out + (size_t)n * TT;
    int base = c * CHUNK;

    // apl = A^(8*lane) by square-and-multiply (underflow for large lane is fine)
    float apl = 1.0f, aa = A8f;
    int e = lane;
    #pragma unroll
    for (int k = 0; k < 5; ++k) { if (e & 1) apl *= aa; aa *= aa; e >>= 1; }

    const float4* p = reinterpret_cast<const float4*>(row + base);
    float4*       q = reinterpret_cast<float4*>(orow + base);

    // Prefetch tile 0 BEFORE the warm-up scan so its latency overlaps.
    float4 xa = __ldcs(p + 2 * lane);
    float4 xb = __ldcs(p + 2 * lane + 1);

    float carry = 0.0f;
    if (c != 0) {
        carry = warm_tile(reinterpret_cast<const float4*>(row + base - 128), lane);
    }

    #pragma unroll
    for (int t = 0; t < TILES; ++t) {
        float4 na, nb;
        if (t + 1 < TILES) {
            na = __ldcs(p + (t + 1) * 64 + 2 * lane);
            nb = __ldcs(p + (t + 1) * 64 + 2 * lane + 1);
        }
        carry = tile_scan256(xa, xb, q + t * 64, carry, apl, lane);
        xa = na; xb = nb;
    }
}

extern "C" void kernel_launch(void* const* d_in, const int* in_sizes, int n_in,
                              void* d_out, int out_size)
{
    const float* in = (const float*)d_in[0];
    float* out = (float*)d_out;
    (void)in_sizes; (void)n_in; (void)out_size;

    int total_warps = NN * NCHUNK;            // 16384
    int block = 256;                          // 8 warps
    int grid = total_warps * 32 / block;      // 2048
    nonspiking_warpscan256_kernel<<<grid, block>>>(in, out);
}